// round 4
// baseline (speedup 1.0000x reference)
#include <cuda_runtime.h>

// ---------------- scratch (device globals; no allocation allowed) ----------------
__device__ float g_A1[221184];    // layer1 eff weights: [(o*9+j)][kk(96)][n(16)]
__device__ float g_A2[688128];    // layer2 eff weights: [j][kk(384)][col(256)] col=o*8+n
__device__ float g_t1[4718592];   // [b][c16][j9][n8]
__device__ float g_t2[3670016];   // [b][c32][j7][l4]
__device__ float g_t3[1310720];   // [b][o*5+j]
__device__ float g_red[224];      // sum1[16] ssq1[16] sum2[32] ssq2[32] sum3[64] ssq3[64]
__device__ float g_bn1[32];       // [scale16][shift16]
__device__ float g_bn2[64];       // [scale32][shift32]
__device__ float g_bn3[128];      // [scale64][shift64]

__global__ void k_zero() {
    if (threadIdx.x < 224) g_red[threadIdx.x] = 0.f;
}

// Build layer1 effective weights. A1[(o,j)][kk=c*16+p][n]
// = sum_m w1[o,c,m] * hat((p-n)/h - m)/h, support clipped to |p-n| <= 3h.
__global__ void k_prep1(const float* __restrict__ w1) {
    int id = blockIdx.x * blockDim.x + threadIdx.x;
    if (id >= 221184) return;
    int n  = id & 15;
    int kk = (id >> 4) % 96;
    int oj = id / 1536;
    int o = oj / 9, j = oj % 9;
    int c = kk >> 4, p = kk & 15;
    int h = 1 << j;
    int d = p - n;
    float v = 0.f;
    if (d >= -3 * h && d <= 3 * h) {
        float t = (float)d / (float)h;
        #pragma unroll
        for (int mm = 0; mm < 7; mm++) {
            float hat = 1.f - fabsf(t - (float)(mm - 3));
            if (hat > 0.f) v += w1[(o * 6 + c) * 7 + mm] * hat;
        }
        v /= (float)h;
    }
    g_A1[id] = v;
}

// Build layer2 effective weights. A2[j][kk=(c*3+r)*8+p][col=o*8+n]
__global__ void k_prep2(const float* __restrict__ w2) {
    int id = blockIdx.x * blockDim.x + threadIdx.x;
    if (id >= 688128) return;
    int col = id & 255;
    int kk  = (id >> 8) % 384;
    int j   = id / 98304;
    int o = col >> 3, n = col & 7;
    int p = kk & 7;
    int cr = kk >> 3;               // c*3+r
    int h = 1 << j;
    int d = p - n;
    float v = 0.f;
    if (d >= -h && d <= h) {
        float t = (float)d / (float)h;
        #pragma unroll
        for (int mm = 0; mm < 3; mm++) {
            float hat = 1.f - fabsf(t - (float)(mm - 1));
            if (hat > 0.f) v += w2[(o * 48 + cr) * 3 + mm] * hat;
        }
        v /= (float)h;
    }
    g_A2[id] = v;
}

// ---------------------------------------------------------------------------
// Layer1: C[4096 x 2304] = X[4096 x 96] * A1[96 x 2304], fused pool+relu+stats.
// Block: 64 rows x 64 cols (4 oj groups of 16 n). 64 threads, 8x8 micro-tile.
// smem: aR[64][98] (6272) | wS[96][64] (6144) | sblk[32]. pre[64][69] reuses aR.
// ---------------------------------------------------------------------------
__global__ void __launch_bounds__(64) k_layer1(const float* __restrict__ x) {
    extern __shared__ float sm[];
    float* aR   = sm;             // [64][98]
    float* wS   = sm + 6272;      // [96][64]
    float* sblk = sm + 12416;     // [32]
    const int t = threadIdx.x;
    const int b0  = blockIdx.x * 64;
    const int oj0 = blockIdx.y * 4;

    // Load X tile (coalesced), row-major, stride 98
    for (int i = t; i < 6144; i += 64) {
        int r = i / 96, kk = i - r * 96;
        aR[r * 98 + kk] = x[(b0 + r) * 96 + kk];
    }
    // Load W tile: wS[k][g*16+n] = A1[(oj0+g)][k][n]
    for (int i = t; i < 6144; i += 64) {
        int k = i >> 6, col = i & 63;
        int g = col >> 4, n = col & 15;
        wS[i] = g_A1[(oj0 + g) * 1536 + k * 16 + n];
    }
    __syncthreads();

    const int rg = t & 7, cg = t >> 3;   // rows rg+8i, cols cg*8..cg*8+7
    float acc[8][8];
    #pragma unroll
    for (int i = 0; i < 8; i++)
        #pragma unroll
        for (int jc = 0; jc < 8; jc++) acc[i][jc] = 0.f;

    const float* wp = wS + cg * 8;
    #pragma unroll 2
    for (int k = 0; k < 96; k++) {
        float a[8];
        #pragma unroll
        for (int i = 0; i < 8; i++) a[i] = aR[(rg + 8 * i) * 98 + k];
        float4 w0 = *reinterpret_cast<const float4*>(wp + k * 64);
        float4 w1 = *reinterpret_cast<const float4*>(wp + k * 64 + 4);
        float w[8] = {w0.x, w0.y, w0.z, w0.w, w1.x, w1.y, w1.z, w1.w};
        #pragma unroll
        for (int i = 0; i < 8; i++)
            #pragma unroll
            for (int jc = 0; jc < 8; jc++) acc[i][jc] += a[i] * w[jc];
    }
    __syncthreads();

    // Store pre-activations to smem (reuse aR region), stride 69 (conflict-free pool reads)
    float* pre = sm;
    #pragma unroll
    for (int i = 0; i < 8; i++)
        #pragma unroll
        for (int jc = 0; jc < 8; jc++)
            pre[(rg + 8 * i) * 69 + cg * 8 + jc] = acc[i][jc];
    if (t < 32) sblk[t] = 0.f;
    __syncthreads();

    // Pool(4,s2,p1) + relu + stats. Thread = one row.
    const int row = t;
    const float* pr = pre + row * 69;
    const int oA = oj0 / 9, oB = (oj0 + 3) / 9;
    float s0 = 0, ss0 = 0, s1 = 0, ss1 = 0;
    long base = (long)(b0 + row) * 1152;
    #pragma unroll
    for (int g = 0; g < 4; g++) {
        int oj = oj0 + g;
        int o = oj / 9, j = oj - o * 9;
        float* dst = g_t1 + base + o * 72 + j * 8;
        float m8[8];
        #pragma unroll
        for (int k = 0; k < 8; k++) {
            int lo = (2 * k - 1 < 0) ? 0 : 2 * k - 1;
            int hi = (2 * k + 2 > 15) ? 15 : 2 * k + 2;
            float m = pr[g * 16 + lo];
            for (int nn = lo + 1; nn <= hi; nn++) m = fmaxf(m, pr[g * 16 + nn]);
            m = fmaxf(m, 0.f);
            m8[k] = m;
            if (o == oA) { s0 += m; ss0 += m * m; } else { s1 += m; ss1 += m * m; }
        }
        *reinterpret_cast<float4*>(dst)     = make_float4(m8[0], m8[1], m8[2], m8[3]);
        *reinterpret_cast<float4*>(dst + 4) = make_float4(m8[4], m8[5], m8[6], m8[7]);
    }
    atomicAdd(&sblk[oA], s0); atomicAdd(&sblk[16 + oA], ss0);
    if (oB != oA) { atomicAdd(&sblk[oB], s1); atomicAdd(&sblk[16 + oB], ss1); }
    __syncthreads();
    if (t < 16) {
        if (sblk[t] != 0.f)      atomicAdd(&g_red[t], sblk[t]);
        if (sblk[16 + t] != 0.f) atomicAdd(&g_red[16 + t], sblk[16 + t]);
    }
}

__global__ void k_bnparam(const float* __restrict__ g, const float* __restrict__ b, int layer) {
    int c = threadIdx.x;
    int nch, off; float count; float* bn;
    if (layer == 1)      { nch = 16; off = 0;  count = 294912.f; bn = g_bn1; }
    else if (layer == 2) { nch = 32; off = 32; count = 114688.f; bn = g_bn2; }
    else                 { nch = 64; off = 96; count = 20480.f;  bn = g_bn3; }
    if (c >= nch) return;
    float sum = g_red[off + c], ssq = g_red[off + nch + c];
    float mean = sum / count;
    float var = ssq / count - mean * mean;
    float sc = g[c] * rsqrtf(var + 2e-5f);
    bn[c] = sc;
    bn[nch + c] = b[c] - mean * sc;
}

// ---------------------------------------------------------------------------
// Layer2: for each j: C[4096 x 256] = acts[4096 x 384] * A2[j][384 x 256],
// BN1 folded into act load, fused pool+relu+stats.
// Block: 64 rows x 64 cols (8 o2 x 8 n). 64 threads, 8x8 micro. K in 4 tiles of 96.
// ---------------------------------------------------------------------------
__global__ void __launch_bounds__(64) k_layer2() {
    extern __shared__ float sm[];
    float* aR   = sm;             // [64][98]
    float* wS   = sm + 6272;      // [96][64]
    float* sblk = sm + 12416;     // [16]
    const int t = threadIdx.x;
    const int b0 = blockIdx.x * 64;
    const int nb = blockIdx.y;    // o2 block: channels nb*8..nb*8+7
    const int j  = blockIdx.z;

    const int rg = t & 7, cg = t >> 3;
    float acc[8][8];
    #pragma unroll
    for (int i = 0; i < 8; i++)
        #pragma unroll
        for (int jc = 0; jc < 8; jc++) acc[i][jc] = 0.f;

    const float* wbase = g_A2 + j * 98304 + nb * 64;
    for (int kt = 0; kt < 4; kt++) {
        // acts tile (BN1 folded)
        for (int i = t; i < 6144; i += 64) {
            int r = i / 96, kk = i - r * 96;
            int k = kt * 96 + kk;
            int c = k / 24, rem = k - c * 24;
            float v = g_t1[(long)(b0 + r) * 1152 + c * 72 + j * 8 + rem];
            aR[r * 98 + kk] = v * g_bn1[c] + g_bn1[16 + c];
        }
        // weight tile
        for (int i = t; i < 6144; i += 64) {
            int kk = i >> 6, col = i & 63;
            wS[i] = wbase[(kt * 96 + kk) * 256 + col];
        }
        __syncthreads();

        const float* wp = wS + cg * 8;
        #pragma unroll 2
        for (int k = 0; k < 96; k++) {
            float a[8];
            #pragma unroll
            for (int i = 0; i < 8; i++) a[i] = aR[(rg + 8 * i) * 98 + k];
            float4 w0 = *reinterpret_cast<const float4*>(wp + k * 64);
            float4 w1 = *reinterpret_cast<const float4*>(wp + k * 64 + 4);
            float w[8] = {w0.x, w0.y, w0.z, w0.w, w1.x, w1.y, w1.z, w1.w};
            #pragma unroll
            for (int i = 0; i < 8; i++)
                #pragma unroll
                for (int jc = 0; jc < 8; jc++) acc[i][jc] += a[i] * w[jc];
        }
        __syncthreads();
    }

    // Epilogue: pre[64][69] reuses aR
    float* pre = sm;
    #pragma unroll
    for (int i = 0; i < 8; i++)
        #pragma unroll
        for (int jc = 0; jc < 8; jc++)
            pre[(rg + 8 * i) * 69 + cg * 8 + jc] = acc[i][jc];
    if (t < 16) sblk[t] = 0.f;
    __syncthreads();

    const int row = t;
    const float* pr = pre + row * 69;
    long tbase = (long)(b0 + row) * 896 + j * 4;
    #pragma unroll
    for (int ol = 0; ol < 8; ol++) {
        float s = 0, ss = 0;
        float m4[4];
        #pragma unroll
        for (int k = 0; k < 4; k++) {
            int lo = (2 * k - 1 < 0) ? 0 : 2 * k - 1;
            int hi = (2 * k + 2 > 7) ? 7 : 2 * k + 2;
            float m = pr[ol * 8 + lo];
            for (int nn = lo + 1; nn <= hi; nn++) m = fmaxf(m, pr[ol * 8 + nn]);
            m = fmaxf(m, 0.f);
            m4[k] = m;
            s += m; ss += m * m;
        }
        *reinterpret_cast<float4*>(g_t2 + tbase + (nb * 8 + ol) * 28) =
            make_float4(m4[0], m4[1], m4[2], m4[3]);
        atomicAdd(&sblk[ol], s);
        atomicAdd(&sblk[8 + ol], ss);
    }
    __syncthreads();
    if (t < 8) {
        atomicAdd(&g_red[32 + nb * 8 + t], sblk[t]);
        atomicAdd(&g_red[64 + nb * 8 + t], sblk[8 + t]);
    }
}

// Layer3: per batch-tile of 16: full t2 slice in smem (BN2 folded on load),
// contraction over (c=32, k=3); weights transposed [k][o3] (conflict-free).
__global__ void __launch_bounds__(256) k_layer3(const float* __restrict__ w3) {
    extern __shared__ float sm[];          // acts 14336 | ws 6144
    __shared__ float st[128];
    float* acts = sm;
    float* ws = sm + 14336;                // ws[kidx][o3], kidx = c*3+r
    int t = threadIdx.x;
    int b0 = blockIdx.x * 16;
    for (int i = t; i < 14336; i += 256) {
        int k = i % 896;
        int c = k / 28;
        acts[i] = g_t2[b0 * 896 + i] * g_bn2[c] + g_bn2[32 + c];
    }
    for (int i = t; i < 6144; i += 256) {
        int kidx = i >> 6, o = i & 63;
        int c = kidx / 3, rr = kidx - c * 3;
        ws[i] = w3[(o * 32 + c) * 3 + rr];  // w3[...,0]: last dim is 1
    }
    __syncthreads();

    int o3 = t & 63, rb = t >> 6;
    const float invj[5] = {1.f, 0.5f, 0.25f, 0.125f, 0.0625f};
    float s = 0, ssq = 0;
    for (int q = 0; q < 4; q++) {
        int row = rb * 4 + q;
        const float* arow = acts + row * 896;
        float accs[15];
        #pragma unroll
        for (int i = 0; i < 15; i++) accs[i] = 0.f;
        for (int c = 0; c < 32; c++) {
            float a[28];
            const float4* a4 = reinterpret_cast<const float4*>(arow + c * 28);
            #pragma unroll
            for (int i4 = 0; i4 < 7; i4++) {
                float4 v = a4[i4];
                a[i4 * 4] = v.x; a[i4 * 4 + 1] = v.y; a[i4 * 4 + 2] = v.z; a[i4 * 4 + 3] = v.w;
            }
            float w0  = ws[(c * 3 + 0) * 64 + o3];
            float w1v = ws[(c * 3 + 1) * 64 + o3];
            float w2v = ws[(c * 3 + 2) * 64 + o3];
            #pragma unroll
            for (int jj = 0; jj < 5; jj++)
                #pragma unroll
                for (int l = 0; l < 3; l++)
                    accs[jj * 3 + l] += w0 * a[jj * 4 + l]
                                      + w1v * a[(jj + 1) * 4 + l]
                                      + w2v * a[(jj + 2) * 4 + l];
        }
        #pragma unroll
        for (int jj = 0; jj < 5; jj++) {
            float m = fmaxf(fmaxf(accs[jj * 3], accs[jj * 3 + 1]), accs[jj * 3 + 2]);
            m = fmaxf(m * invj[jj], 0.f);
            g_t3[(b0 + row) * 320 + o3 * 5 + jj] = m;
            s += m; ssq += m * m;
        }
    }
    if (t < 128) st[t] = 0.f;
    __syncthreads();
    atomicAdd(&st[o3], s);
    atomicAdd(&st[64 + o3], ssq);
    __syncthreads();
    if (t < 64) { atomicAdd(&g_red[96 + t], st[t]); atomicAdd(&g_red[160 + t], st[64 + t]); }
}

// BN3 + 3-layer MLP. One thread per sample; t3 tiles staged through smem.
__global__ void __launch_bounds__(128) k_fc(const float* __restrict__ fw1, const float* __restrict__ fb1,
                                            const float* __restrict__ fw2, const float* __restrict__ fb2,
                                            const float* __restrict__ fw3, const float* __restrict__ fb3,
                                            float* __restrict__ out) {
    __shared__ float w1s[5120];            // transposed [k][o]
    __shared__ float vt[128 * 33];
    __shared__ float w2s[256];
    __shared__ float w3s[272];
    __shared__ float b1s[16], b2s[16], b3s[17];
    int t = threadIdx.x;
    int bbase = blockIdx.x * 128;
    for (int i = t; i < 5120; i += 128) { int o = i / 320, k = i % 320; w1s[k * 16 + o] = fw1[i]; }
    for (int i = t; i < 256; i += 128) w2s[i] = fw2[i];
    for (int i = t; i < 272; i += 128) w3s[i] = fw3[i];
    if (t < 16) { b1s[t] = fb1[t]; b2s[t] = fb2[t]; }
    if (t < 17) b3s[t] = fb3[t];
    __syncthreads();

    float h1[16];
    #pragma unroll
    for (int o = 0; o < 16; o++) h1[o] = b1s[o];

    for (int i0 = 0; i0 < 320; i0 += 32) {
        __syncthreads();
        for (int idx = t; idx < 4096; idx += 128) {
            int r = idx >> 5, c2 = idx & 31;
            int i = i0 + c2, ch = i / 5;
            vt[r * 33 + c2] = g_t3[(bbase + r) * 320 + i] * g_bn3[ch] + g_bn3[64 + ch];
        }
        __syncthreads();
        #pragma unroll 4
        for (int c2 = 0; c2 < 32; c2++) {
            float v = vt[t * 33 + c2];
            const float* wr = &w1s[(i0 + c2) * 16];
            #pragma unroll
            for (int o = 0; o < 16; o++) h1[o] += v * wr[o];
        }
    }
    float h2[16];
    #pragma unroll
    for (int o = 0; o < 16; o++) {
        float a = b2s[o];
        #pragma unroll
        for (int k = 0; k < 16; k++) a += h1[k] * w2s[o * 16 + k];
        h2[o] = a;
    }
    int b = bbase + t;
    #pragma unroll
    for (int o = 0; o < 17; o++) {
        float a = b3s[o];
        #pragma unroll
        for (int k = 0; k < 16; k++) a += h2[k] * w3s[o * 16 + k];
        out[b * 17 + o] = a;
    }
}

extern "C" void kernel_launch(void* const* d_in, const int* in_sizes, int n_in,
                              void* d_out, int out_size) {
    const float* x   = (const float*)d_in[0];
    const float* w1  = (const float*)d_in[1];
    const float* w2  = (const float*)d_in[2];
    const float* w3  = (const float*)d_in[3];
    const float* g1  = (const float*)d_in[4];
    const float* b1  = (const float*)d_in[5];
    const float* g2  = (const float*)d_in[6];
    const float* b2  = (const float*)d_in[7];
    const float* g3  = (const float*)d_in[8];
    const float* b3  = (const float*)d_in[9];
    const float* fw1 = (const float*)d_in[10];
    const float* fb1 = (const float*)d_in[11];
    const float* fw2 = (const float*)d_in[12];
    const float* fb2 = (const float*)d_in[13];
    const float* fw3 = (const float*)d_in[14];
    const float* fb3 = (const float*)d_in[15];
    float* out = (float*)d_out;

    cudaFuncSetAttribute(k_layer1, cudaFuncAttributeMaxDynamicSharedMemorySize, 49792);
    cudaFuncSetAttribute(k_layer2, cudaFuncAttributeMaxDynamicSharedMemorySize, 49728);
    cudaFuncSetAttribute(k_layer3, cudaFuncAttributeMaxDynamicSharedMemorySize, 81920);

    k_zero<<<1, 256>>>();
    k_prep1<<<(221184 + 255) / 256, 256>>>(w1);
    k_prep2<<<(688128 + 255) / 256, 256>>>(w2);
    k_layer1<<<dim3(64, 36), 64, 49792>>>(x);
    k_bnparam<<<1, 64>>>(g1, b1, 1);
    k_layer2<<<dim3(64, 4, 7), 64, 49728>>>();
    k_bnparam<<<1, 64>>>(g2, b2, 2);
    k_layer3<<<256, 256, 81920>>>(w3);
    k_bnparam<<<1, 64>>>(g3, b3, 3);
    k_fc<<<32, 128>>>(fw1, fb1, fw2, fb2, fw3, fb3, out);
}

// round 5
// speedup vs baseline: 2.2667x; 2.2667x over previous
#include <cuda_runtime.h>

// ---------------- scratch (device globals; no allocation allowed) ----------------
__device__ float g_A1[221184];    // layer1 eff weights: [(o*9+j)][kk(96)][n(16)]
__device__ float g_A2[688128];    // layer2 eff weights: [j][kk(384)][col(256)] col=o*8+n
__device__ float g_t1[4718592];   // [b][c16][j9][n8]
__device__ float g_t2[3670016];   // [b][c32][j7][l4]
__device__ float g_t3[1310720];   // [b][o*5+j]
__device__ float g_red[224];      // sum1[16] ssq1[16] sum2[32] ssq2[32] sum3[64] ssq3[64]
__device__ float g_bn1[32];       // [scale16][shift16]
__device__ float g_bn2[64];       // [scale32][shift32]
__device__ float g_bn3[128];      // [scale64][shift64]

__device__ __forceinline__ void fma2(unsigned long long& d, unsigned long long a, unsigned long long b) {
    asm("fma.rn.f32x2 %0, %1, %2, %0;" : "+l"(d) : "l"(a), "l"(b));
}
__device__ __forceinline__ float warp_sum(float v) {
    #pragma unroll
    for (int o = 16; o; o >>= 1) v += __shfl_down_sync(0xffffffffu, v, o);
    return v;
}

__global__ void k_zero() {
    if (threadIdx.x < 224) g_red[threadIdx.x] = 0.f;
}

// Build layer1 effective weights. A1[(o,j)][kk=c*16+p][n]
__global__ void k_prep1(const float* __restrict__ w1) {
    int id = blockIdx.x * blockDim.x + threadIdx.x;
    if (id >= 221184) return;
    int n  = id & 15;
    int kk = (id >> 4) % 96;
    int oj = id / 1536;
    int o = oj / 9, j = oj % 9;
    int c = kk >> 4, p = kk & 15;
    int h = 1 << j;
    int d = p - n;
    float v = 0.f;
    if (d >= -3 * h && d <= 3 * h) {
        float t = (float)d / (float)h;
        #pragma unroll
        for (int mm = 0; mm < 7; mm++) {
            float hat = 1.f - fabsf(t - (float)(mm - 3));
            if (hat > 0.f) v += w1[(o * 6 + c) * 7 + mm] * hat;
        }
        v /= (float)h;
    }
    g_A1[id] = v;
}

// Build layer2 effective weights. A2[j][kk=(c*3+r)*8+p][col=o*8+n]
__global__ void k_prep2(const float* __restrict__ w2) {
    int id = blockIdx.x * blockDim.x + threadIdx.x;
    if (id >= 688128) return;
    int col = id & 255;
    int kk  = (id >> 8) % 384;
    int j   = id / 98304;
    int o = col >> 3, n = col & 7;
    int p = kk & 7;
    int cr = kk >> 3;               // c*3+r
    int h = 1 << j;
    int d = p - n;
    float v = 0.f;
    if (d >= -h && d <= h) {
        float t = (float)d / (float)h;
        #pragma unroll
        for (int mm = 0; mm < 3; mm++) {
            float hat = 1.f - fabsf(t - (float)(mm - 1));
            if (hat > 0.f) v += w2[(o * 48 + cr) * 3 + mm] * hat;
        }
        v /= (float)h;
    }
    g_A2[id] = v;
}

// ---------------------------------------------------------------------------
// Layer1: C[4096 x 2304] = X[4096 x 96] * A1[96 x 2304], fused pool+relu+stats.
// Block: 128 rows x 128 cols (8 oj groups of 16 n). 256 threads, 8x8 micro,
// f32x2 packed FMA, duplicated-a smem. K in 2 tiles of 48.
// smem floats: aD[128][98] (dup a) = 12544 | wS[48][128] = 6144  => 74752 B
// ---------------------------------------------------------------------------
__global__ void __launch_bounds__(256, 2) k_layer1(const float* __restrict__ x) {
    extern __shared__ float sm[];
    float* aD = sm;               // [128][98]: row r, k-pair at 2k (dup)
    float* wS = sm + 12544;       // [48][128]
    const int t = threadIdx.x;
    const int b0  = blockIdx.x * 128;
    const int oj0 = blockIdx.y * 8;

    const int rg = t & 15, cg = t >> 4;   // rows rg+16i (i<8), cols cg*8..+7
    unsigned long long acc[8][4];
    #pragma unroll
    for (int i = 0; i < 8; i++)
        #pragma unroll
        for (int p = 0; p < 4; p++) acc[i][p] = 0ull;

    const unsigned long long* a64 = reinterpret_cast<const unsigned long long*>(aD);
    const unsigned long long* w64 = reinterpret_cast<const unsigned long long*>(wS);

    for (int kt = 0; kt < 2; kt++) {
        __syncthreads();
        // acts: 128 rows x 48 k, duplicated
        for (int i = t; i < 6144; i += 256) {
            int r = i / 48, kk = i - r * 48;
            float v = x[(b0 + r) * 96 + kt * 48 + kk];
            *reinterpret_cast<float2*>(aD + r * 98 + 2 * kk) = make_float2(v, v);
        }
        // weights: 48 k x 128 cols (col = g*16+n)
        for (int i = t; i < 6144; i += 256) {
            int kk = i >> 7, col = i & 127;
            int g = col >> 4, n = col & 15;
            wS[i] = g_A1[(oj0 + g) * 1536 + (kt * 48 + kk) * 16 + n];
        }
        __syncthreads();

        #pragma unroll 4
        for (int k = 0; k < 48; k++) {
            unsigned long long av[8];
            #pragma unroll
            for (int i = 0; i < 8; i++) av[i] = a64[(rg + 16 * i) * 49 + k];
            unsigned long long wv[4];
            #pragma unroll
            for (int p = 0; p < 4; p++) wv[p] = w64[k * 64 + cg * 4 + p];
            #pragma unroll
            for (int i = 0; i < 8; i++)
                #pragma unroll
                for (int p = 0; p < 4; p++) fma2(acc[i][p], av[i], wv[p]);
        }
    }
    __syncthreads();

    // pre[128][129] reuses smem
    float* pre = sm;
    #pragma unroll
    for (int i = 0; i < 8; i++)
        #pragma unroll
        for (int p = 0; p < 4; p++) {
            float2 v = *reinterpret_cast<float2*>(&acc[i][p]);
            pre[(rg + 16 * i) * 129 + cg * 8 + 2 * p]     = v.x;
            pre[(rg + 16 * i) * 129 + cg * 8 + 2 * p + 1] = v.y;
        }
    __syncthreads();

    // Pool(4,s2,p1)+relu+stats. thread = (row = t&127, half = t>>7) -> 4 oj groups
    const int row = t & 127, half = t >> 7;
    const float* pr = pre + row * 129;
    long base = (long)(b0 + row) * 1152;
    #pragma unroll
    for (int gg = 0; gg < 4; gg++) {
        int g = half * 4 + gg;
        int oj = oj0 + g;
        int o = oj / 9, jj = oj - o * 9;
        float* dst = g_t1 + base + o * 72 + jj * 8;
        float s = 0.f, ss = 0.f;
        float m8[8];
        #pragma unroll
        for (int k = 0; k < 8; k++) {
            int lo = (2 * k - 1 < 0) ? 0 : 2 * k - 1;
            int hi = (2 * k + 2 > 15) ? 15 : 2 * k + 2;
            float m = pr[g * 16 + lo];
            for (int nn = lo + 1; nn <= hi; nn++) m = fmaxf(m, pr[g * 16 + nn]);
            m = fmaxf(m, 0.f);
            m8[k] = m;
            s += m; ss += m * m;
        }
        *reinterpret_cast<float4*>(dst)     = make_float4(m8[0], m8[1], m8[2], m8[3]);
        *reinterpret_cast<float4*>(dst + 4) = make_float4(m8[4], m8[5], m8[6], m8[7]);
        // o is warp-uniform (g, oj0 uniform): warp-reduce then single atomic
        float sA = warp_sum(s), ssA = warp_sum(ss);
        if ((t & 31) == 0) {
            atomicAdd(&g_red[o], sA);
            atomicAdd(&g_red[16 + o], ssA);
        }
    }
}

__global__ void k_bnparam(const float* __restrict__ g, const float* __restrict__ b, int layer) {
    int c = threadIdx.x;
    int nch, off; float count; float* bn;
    if (layer == 1)      { nch = 16; off = 0;  count = 294912.f; bn = g_bn1; }
    else if (layer == 2) { nch = 32; off = 32; count = 114688.f; bn = g_bn2; }
    else                 { nch = 64; off = 96; count = 20480.f;  bn = g_bn3; }
    if (c >= nch) return;
    float sum = g_red[off + c], ssq = g_red[off + nch + c];
    float mean = sum / count;
    float var = ssq / count - mean * mean;
    float sc = g[c] * rsqrtf(var + 2e-5f);
    bn[c] = sc;
    bn[nch + c] = b[c] - mean * sc;
}

// ---------------------------------------------------------------------------
// Layer2: per j: C[4096 x 256] = acts[4096 x 384] * A2[j], BN1 folded,
// fused pool+relu+stats. Block: 128 rows x 128 cols (16 o2), 256 threads,
// 8x8 micro, f32x2, dup-a. K in 6 tiles of 64.
// smem floats: aD[128][130] = 16640 | wS[64][128] = 8192  => 99328 B
// ---------------------------------------------------------------------------
__global__ void __launch_bounds__(256, 2) k_layer2() {
    extern __shared__ float sm[];
    __shared__ float bnS[32];
    float* aD = sm;               // [128][130]
    float* wS = sm + 16640;       // [64][128]
    const int t = threadIdx.x;
    const int b0 = blockIdx.x * 128;
    const int cb = blockIdx.y;    // col block: o2 channels cb*16..+15
    const int j  = blockIdx.z;

    if (t < 32) bnS[t] = g_bn1[t];

    const int rg = t & 15, cg = t >> 4;
    unsigned long long acc[8][4];
    #pragma unroll
    for (int i = 0; i < 8; i++)
        #pragma unroll
        for (int p = 0; p < 4; p++) acc[i][p] = 0ull;

    const unsigned long long* a64 = reinterpret_cast<const unsigned long long*>(aD);
    const unsigned long long* w64 = reinterpret_cast<const unsigned long long*>(wS);
    const float* wbase = g_A2 + j * 98304 + cb * 128;

    for (int kt = 0; kt < 6; kt++) {
        __syncthreads();
        // acts tile: 128 rows x 64 k (BN1 folded, duplicated)
        for (int i = t; i < 8192; i += 256) {
            int r = i >> 6, kk = i & 63;
            int k = kt * 64 + kk;
            int c = k / 24, rem = k - c * 24;
            float v = g_t1[(long)(b0 + r) * 1152 + c * 72 + j * 8 + rem];
            v = v * bnS[c] + bnS[16 + c];
            *reinterpret_cast<float2*>(aD + r * 130 + 2 * kk) = make_float2(v, v);
        }
        // weight tile: 64 k x 128 cols
        for (int i = t; i < 8192; i += 256) {
            int kk = i >> 7, col = i & 127;
            wS[i] = wbase[(kt * 64 + kk) * 256 + col];
        }
        __syncthreads();

        #pragma unroll 4
        for (int k = 0; k < 64; k++) {
            unsigned long long av[8];
            #pragma unroll
            for (int i = 0; i < 8; i++) av[i] = a64[(rg + 16 * i) * 65 + k];
            unsigned long long wv[4];
            #pragma unroll
            for (int p = 0; p < 4; p++) wv[p] = w64[k * 64 + cg * 4 + p];
            #pragma unroll
            for (int i = 0; i < 8; i++)
                #pragma unroll
                for (int p = 0; p < 4; p++) fma2(acc[i][p], av[i], wv[p]);
        }
    }
    __syncthreads();

    float* pre = sm;              // [128][129]
    #pragma unroll
    for (int i = 0; i < 8; i++)
        #pragma unroll
        for (int p = 0; p < 4; p++) {
            float2 v = *reinterpret_cast<float2*>(&acc[i][p]);
            pre[(rg + 16 * i) * 129 + cg * 8 + 2 * p]     = v.x;
            pre[(rg + 16 * i) * 129 + cg * 8 + 2 * p + 1] = v.y;
        }
    __syncthreads();

    // Pool(4,s2,p1)+relu+stats. thread = (row, half) -> 8 o2 channels
    const int row = t & 127, half = t >> 7;
    const float* pr = pre + row * 129;
    long tbase = (long)(b0 + row) * 896 + j * 4;
    #pragma unroll
    for (int ol = 0; ol < 8; ol++) {
        int lc = half * 8 + ol;             // local col group (o2 within block)
        int o2g = cb * 16 + lc;             // global o2 channel
        float s = 0.f, ss = 0.f;
        float m4[4];
        #pragma unroll
        for (int k = 0; k < 4; k++) {
            int lo = (2 * k - 1 < 0) ? 0 : 2 * k - 1;
            int hi = (2 * k + 2 > 7) ? 7 : 2 * k + 2;
            float m = pr[lc * 8 + lo];
            for (int nn = lo + 1; nn <= hi; nn++) m = fmaxf(m, pr[lc * 8 + nn]);
            m = fmaxf(m, 0.f);
            m4[k] = m;
            s += m; ss += m * m;
        }
        *reinterpret_cast<float4*>(g_t2 + tbase + o2g * 28) =
            make_float4(m4[0], m4[1], m4[2], m4[3]);
        float sA = warp_sum(s), ssA = warp_sum(ss);
        if ((t & 31) == 0) {
            atomicAdd(&g_red[32 + o2g], sA);
            atomicAdd(&g_red[64 + o2g], ssA);
        }
    }
}

// Layer3: per batch-tile of 16: full t2 slice in smem (BN2 folded on load),
// contraction over (c=32, k=3); weights transposed [k][o3] (conflict-free).
__global__ void __launch_bounds__(256) k_layer3(const float* __restrict__ w3) {
    extern __shared__ float sm[];          // acts 14336 | ws 6144
    __shared__ float st[128];
    float* acts = sm;
    float* ws = sm + 14336;                // ws[kidx][o3], kidx = c*3+r
    int t = threadIdx.x;
    int b0 = blockIdx.x * 16;
    for (int i = t; i < 14336; i += 256) {
        int k = i % 896;
        int c = k / 28;
        acts[i] = g_t2[b0 * 896 + i] * g_bn2[c] + g_bn2[32 + c];
    }
    for (int i = t; i < 6144; i += 256) {
        int kidx = i >> 6, o = i & 63;
        int c = kidx / 3, rr = kidx - c * 3;
        ws[i] = w3[(o * 32 + c) * 3 + rr];  // w3[...,0]: last dim is 1
    }
    __syncthreads();

    int o3 = t & 63, rb = t >> 6;
    const float invj[5] = {1.f, 0.5f, 0.25f, 0.125f, 0.0625f};
    float s = 0, ssq = 0;
    for (int q = 0; q < 4; q++) {
        int row = rb * 4 + q;
        const float* arow = acts + row * 896;
        float accs[15];
        #pragma unroll
        for (int i = 0; i < 15; i++) accs[i] = 0.f;
        for (int c = 0; c < 32; c++) {
            float a[28];
            const float4* a4 = reinterpret_cast<const float4*>(arow + c * 28);
            #pragma unroll
            for (int i4 = 0; i4 < 7; i4++) {
                float4 v = a4[i4];
                a[i4 * 4] = v.x; a[i4 * 4 + 1] = v.y; a[i4 * 4 + 2] = v.z; a[i4 * 4 + 3] = v.w;
            }
            float w0  = ws[(c * 3 + 0) * 64 + o3];
            float w1v = ws[(c * 3 + 1) * 64 + o3];
            float w2v = ws[(c * 3 + 2) * 64 + o3];
            #pragma unroll
            for (int jj = 0; jj < 5; jj++)
                #pragma unroll
                for (int l = 0; l < 3; l++)
                    accs[jj * 3 + l] += w0 * a[jj * 4 + l]
                                      + w1v * a[(jj + 1) * 4 + l]
                                      + w2v * a[(jj + 2) * 4 + l];
        }
        #pragma unroll
        for (int jj = 0; jj < 5; jj++) {
            float m = fmaxf(fmaxf(accs[jj * 3], accs[jj * 3 + 1]), accs[jj * 3 + 2]);
            m = fmaxf(m * invj[jj], 0.f);
            g_t3[(b0 + row) * 320 + o3 * 5 + jj] = m;
            s += m; ssq += m * m;
        }
    }
    if (t < 128) st[t] = 0.f;
    __syncthreads();
    atomicAdd(&st[o3], s);
    atomicAdd(&st[64 + o3], ssq);
    __syncthreads();
    if (t < 64) { atomicAdd(&g_red[96 + t], st[t]); atomicAdd(&g_red[160 + t], st[64 + t]); }
}

// BN3 + 3-layer MLP. One thread per sample; t3 tiles staged through smem.
__global__ void __launch_bounds__(128) k_fc(const float* __restrict__ fw1, const float* __restrict__ fb1,
                                            const float* __restrict__ fw2, const float* __restrict__ fb2,
                                            const float* __restrict__ fw3, const float* __restrict__ fb3,
                                            float* __restrict__ out) {
    __shared__ float w1s[5120];            // transposed [k][o]
    __shared__ float vt[128 * 33];
    __shared__ float w2s[256];
    __shared__ float w3s[272];
    __shared__ float b1s[16], b2s[16], b3s[17];
    int t = threadIdx.x;
    int bbase = blockIdx.x * 128;
    for (int i = t; i < 5120; i += 128) { int o = i / 320, k = i % 320; w1s[k * 16 + o] = fw1[i]; }
    for (int i = t; i < 256; i += 128) w2s[i] = fw2[i];
    for (int i = t; i < 272; i += 128) w3s[i] = fw3[i];
    if (t < 16) { b1s[t] = fb1[t]; b2s[t] = fb2[t]; }
    if (t < 17) b3s[t] = fb3[t];
    __syncthreads();

    float h1[16];
    #pragma unroll
    for (int o = 0; o < 16; o++) h1[o] = b1s[o];

    for (int i0 = 0; i0 < 320; i0 += 32) {
        __syncthreads();
        for (int idx = t; idx < 4096; idx += 128) {
            int r = idx >> 5, c2 = idx & 31;
            int i = i0 + c2, ch = i / 5;
            vt[r * 33 + c2] = g_t3[(bbase + r) * 320 + i] * g_bn3[ch] + g_bn3[64 + ch];
        }
        __syncthreads();
        #pragma unroll 4
        for (int c2 = 0; c2 < 32; c2++) {
            float v = vt[t * 33 + c2];
            const float* wr = &w1s[(i0 + c2) * 16];
            #pragma unroll
            for (int o = 0; o < 16; o++) h1[o] += v * wr[o];
        }
    }
    float h2[16];
    #pragma unroll
    for (int o = 0; o < 16; o++) {
        float a = b2s[o];
        #pragma unroll
        for (int k = 0; k < 16; k++) a += h1[k] * w2s[o * 16 + k];
        h2[o] = a;
    }
    int b = bbase + t;
    #pragma unroll
    for (int o = 0; o < 17; o++) {
        float a = b3s[o];
        #pragma unroll
        for (int k = 0; k < 16; k++) a += h2[k] * w3s[o * 16 + k];
        out[b * 17 + o] = a;
    }
}

extern "C" void kernel_launch(void* const* d_in, const int* in_sizes, int n_in,
                              void* d_out, int out_size) {
    const float* x   = (const float*)d_in[0];
    const float* w1  = (const float*)d_in[1];
    const float* w2  = (const float*)d_in[2];
    const float* w3  = (const float*)d_in[3];
    const float* g1  = (const float*)d_in[4];
    const float* b1  = (const float*)d_in[5];
    const float* g2  = (const float*)d_in[6];
    const float* b2  = (const float*)d_in[7];
    const float* g3  = (const float*)d_in[8];
    const float* b3  = (const float*)d_in[9];
    const float* fw1 = (const float*)d_in[10];
    const float* fb1 = (const float*)d_in[11];
    const float* fw2 = (const float*)d_in[12];
    const float* fb2 = (const float*)d_in[13];
    const float* fw3 = (const float*)d_in[14];
    const float* fb3 = (const float*)d_in[15];
    float* out = (float*)d_out;

    cudaFuncSetAttribute(k_layer1, cudaFuncAttributeMaxDynamicSharedMemorySize, 74752);
    cudaFuncSetAttribute(k_layer2, cudaFuncAttributeMaxDynamicSharedMemorySize, 99328);
    cudaFuncSetAttribute(k_layer3, cudaFuncAttributeMaxDynamicSharedMemorySize, 81920);

    k_zero<<<1, 256>>>();
    k_prep1<<<(221184 + 255) / 256, 256>>>(w1);
    k_prep2<<<(688128 + 255) / 256, 256>>>(w2);
    k_layer1<<<dim3(32, 18), 256, 74752>>>(x);
    k_bnparam<<<1, 64>>>(g1, b1, 1);
    k_layer2<<<dim3(32, 2, 7), 256, 99328>>>();
    k_bnparam<<<1, 64>>>(g2, b2, 2);
    k_layer3<<<256, 256, 81920>>>(w3);
    k_bnparam<<<1, 64>>>(g3, b3, 3);
    k_fc<<<32, 128>>>(fw1, fb1, fw2, fb2, fw3, fb3, out);
}

// round 6
// speedup vs baseline: 2.2813x; 1.0064x over previous
#include <cuda_runtime.h>

// ---------------- scratch (device globals; no allocation allowed) ----------------
__device__ float g_A1[221184];    // layer1 eff weights: [(o*9+j)][kk(96)][n(16)]
__device__ float g_A2[688128];    // layer2 eff weights: [j][kk(384)][col(256)] col=o*8+n
__device__ float g_t1[4718592];   // [b][c16][j9][n8]
__device__ float g_t2[3670016];   // [b][c32][j7][l4]
__device__ float g_t3[1310720];   // [b][o*5+j]
__device__ float g_red[224];      // sum1[16] ssq1[16] sum2[32] ssq2[32] sum3[64] ssq3[64]
__device__ float g_bn1[32];       // [scale16][shift16]
__device__ float g_bn2[64];       // [scale32][shift32]
__device__ float g_bn3[128];      // [scale64][shift64]

__device__ __forceinline__ void fma2(unsigned long long& d, unsigned long long a, unsigned long long b) {
    asm("fma.rn.f32x2 %0, %1, %2, %0;" : "+l"(d) : "l"(a), "l"(b));
}
__device__ __forceinline__ float warp_sum(float v) {
    #pragma unroll
    for (int o = 16; o; o >>= 1) v += __shfl_down_sync(0xffffffffu, v, o);
    return v;
}

__global__ void k_zero() {
    if (threadIdx.x < 224) g_red[threadIdx.x] = 0.f;
}

// Build layer1 effective weights. A1[(o,j)][kk=c*16+p][n]
__global__ void k_prep1(const float* __restrict__ w1) {
    int id = blockIdx.x * blockDim.x + threadIdx.x;
    if (id >= 221184) return;
    int n  = id & 15;
    int kk = (id >> 4) % 96;
    int oj = id / 1536;
    int o = oj / 9, j = oj % 9;
    int c = kk >> 4, p = kk & 15;
    int h = 1 << j;
    int d = p - n;
    float v = 0.f;
    if (d >= -3 * h && d <= 3 * h) {
        float t = (float)d / (float)h;
        #pragma unroll
        for (int mm = 0; mm < 7; mm++) {
            float hat = 1.f - fabsf(t - (float)(mm - 3));
            if (hat > 0.f) v += w1[(o * 6 + c) * 7 + mm] * hat;
        }
        v /= (float)h;
    }
    g_A1[id] = v;
}

// Build layer2 effective weights. A2[j][kk=(c*3+r)*8+p][col=o*8+n]
__global__ void k_prep2(const float* __restrict__ w2) {
    int id = blockIdx.x * blockDim.x + threadIdx.x;
    if (id >= 688128) return;
    int col = id & 255;
    int kk  = (id >> 8) % 384;
    int j   = id / 98304;
    int o = col >> 3, n = col & 7;
    int p = kk & 7;
    int cr = kk >> 3;               // c*3+r
    int h = 1 << j;
    int d = p - n;
    float v = 0.f;
    if (d >= -h && d <= h) {
        float t = (float)d / (float)h;
        #pragma unroll
        for (int mm = 0; mm < 3; mm++) {
            float hat = 1.f - fabsf(t - (float)(mm - 1));
            if (hat > 0.f) v += w2[(o * 48 + cr) * 3 + mm] * hat;
        }
        v /= (float)h;
    }
    g_A2[id] = v;
}

// ---------------------------------------------------------------------------
// Layer1: C[4096 x 2304] = X[4096 x 96] * A1[96 x 2304], fused pool+relu+stats.
// Block 128 rows x 128 cols, 256 threads. Row-pair f32x2 accumulation:
//   aT[k][row] transposed (natural row-pair LDS.64), wD[k][2*col] duplicated
//   (broadcast LDS.64). Per k: 4 a-loads + 4 w-loads + 32 FMA2.
// smem floats: aT 48*130=6240 | wD 48*258=12384  => 74496 B. K in 2 tiles of 48.
// ---------------------------------------------------------------------------
__global__ void __launch_bounds__(256, 2) k_layer1(const float* __restrict__ x) {
    extern __shared__ float sm[];
    float* aT = sm;               // [48][130]  (k-major, row minor)
    float* wD = sm + 6240;        // [48][258]  dup cols
    const int t = threadIdx.x;
    const int b0  = blockIdx.x * 128;
    const int oj0 = blockIdx.y * 8;

    const int rg = t & 15, cg = t >> 4;   // row-pairs 2rg+32q, cols cg*8..+7
    unsigned long long acc[4][8];
    #pragma unroll
    for (int q = 0; q < 4; q++)
        #pragma unroll
        for (int c = 0; c < 8; c++) acc[q][c] = 0ull;

    const unsigned long long* a64 = reinterpret_cast<const unsigned long long*>(aT);
    const unsigned long long* w64 = reinterpret_cast<const unsigned long long*>(wD);

    for (int kt = 0; kt < 2; kt++) {
        __syncthreads();
        // acts transposed: aT[kk][r]
        for (int i = t; i < 6144; i += 256) {
            int r = i / 48, kk = i - r * 48;
            aT[kk * 130 + r] = x[(b0 + r) * 96 + kt * 48 + kk];
        }
        // weights duplicated: wD[kk][2*col] = {w,w}
        for (int i = t; i < 6144; i += 256) {
            int kk = i >> 7, col = i & 127;
            int g = col >> 4, n = col & 15;
            float v = g_A1[(oj0 + g) * 1536 + (kt * 48 + kk) * 16 + n];
            *reinterpret_cast<float2*>(wD + kk * 258 + 2 * col) = make_float2(v, v);
        }
        __syncthreads();

        #pragma unroll 4
        for (int k = 0; k < 48; k++) {
            unsigned long long av[4];
            #pragma unroll
            for (int q = 0; q < 4; q++) av[q] = a64[k * 65 + rg + 16 * q];
            unsigned long long wv[8];
            #pragma unroll
            for (int c = 0; c < 8; c++) wv[c] = w64[k * 129 + cg * 8 + c];
            #pragma unroll
            for (int q = 0; q < 4; q++)
                #pragma unroll
                for (int c = 0; c < 8; c++) fma2(acc[q][c], av[q], wv[c]);
        }
    }
    __syncthreads();

    // pre[128][129] reuses smem
    float* pre = sm;
    #pragma unroll
    for (int q = 0; q < 4; q++)
        #pragma unroll
        for (int c = 0; c < 8; c++) {
            float2 v = *reinterpret_cast<float2*>(&acc[q][c]);
            int r0 = 2 * rg + 32 * q;
            pre[r0 * 129 + cg * 8 + c]       = v.x;
            pre[(r0 + 1) * 129 + cg * 8 + c] = v.y;
        }
    __syncthreads();

    // Pool(4,s2,p1)+relu+stats. thread = (row = t&127, half = t>>7) -> 4 oj groups
    const int row = t & 127, half = t >> 7;
    const float* pr = pre + row * 129;
    long base = (long)(b0 + row) * 1152;
    #pragma unroll
    for (int gg = 0; gg < 4; gg++) {
        int g = half * 4 + gg;
        int oj = oj0 + g;
        int o = oj / 9, jj = oj - o * 9;
        float* dst = g_t1 + base + o * 72 + jj * 8;
        float s = 0.f, ss = 0.f;
        float m8[8];
        #pragma unroll
        for (int k = 0; k < 8; k++) {
            int lo = (2 * k - 1 < 0) ? 0 : 2 * k - 1;
            int hi = (2 * k + 2 > 15) ? 15 : 2 * k + 2;
            float m = pr[g * 16 + lo];
            for (int nn = lo + 1; nn <= hi; nn++) m = fmaxf(m, pr[g * 16 + nn]);
            m = fmaxf(m, 0.f);
            m8[k] = m;
            s += m; ss += m * m;
        }
        *reinterpret_cast<float4*>(dst)     = make_float4(m8[0], m8[1], m8[2], m8[3]);
        *reinterpret_cast<float4*>(dst + 4) = make_float4(m8[4], m8[5], m8[6], m8[7]);
        float sA = warp_sum(s), ssA = warp_sum(ss);
        if ((t & 31) == 0) {
            atomicAdd(&g_red[o], sA);
            atomicAdd(&g_red[16 + o], ssA);
        }
    }
}

__global__ void k_bnparam(const float* __restrict__ g, const float* __restrict__ b, int layer) {
    int c = threadIdx.x;
    int nch, off; float count; float* bn;
    if (layer == 1)      { nch = 16; off = 0;  count = 294912.f; bn = g_bn1; }
    else if (layer == 2) { nch = 32; off = 32; count = 114688.f; bn = g_bn2; }
    else                 { nch = 64; off = 96; count = 20480.f;  bn = g_bn3; }
    if (c >= nch) return;
    float sum = g_red[off + c], ssq = g_red[off + nch + c];
    float mean = sum / count;
    float var = ssq / count - mean * mean;
    float sc = g[c] * rsqrtf(var + 2e-5f);
    bn[c] = sc;
    bn[nch + c] = b[c] - mean * sc;
}

// ---------------------------------------------------------------------------
// Layer2: per j: C[4096 x 256] = acts[4096 x 384] * A2[j], BN1 folded,
// fused pool+relu+stats. Block 128 rows x 128 cols, 256 threads, row-pair
// f32x2 scheme. K in 6 tiles of 64.
// smem floats: aT 64*130=8320 | wD 64*258=16512  => 99328 B
// ---------------------------------------------------------------------------
__global__ void __launch_bounds__(256, 2) k_layer2() {
    extern __shared__ float sm[];
    __shared__ float bnS[32];
    float* aT = sm;               // [64][130]
    float* wD = sm + 8320;        // [64][258]
    const int t = threadIdx.x;
    const int b0 = blockIdx.x * 128;
    const int cb = blockIdx.y;    // col block: o2 channels cb*16..+15
    const int j  = blockIdx.z;

    if (t < 32) bnS[t] = g_bn1[t];

    const int rg = t & 15, cg = t >> 4;
    unsigned long long acc[4][8];
    #pragma unroll
    for (int q = 0; q < 4; q++)
        #pragma unroll
        for (int c = 0; c < 8; c++) acc[q][c] = 0ull;

    const unsigned long long* a64 = reinterpret_cast<const unsigned long long*>(aT);
    const unsigned long long* w64 = reinterpret_cast<const unsigned long long*>(wD);
    const float* wbase = g_A2 + j * 98304 + cb * 128;

    for (int kt = 0; kt < 6; kt++) {
        __syncthreads();
        // acts tile transposed (BN1 folded): aT[kk][r]
        for (int i = t; i < 8192; i += 256) {
            int r = i >> 6, kk = i & 63;
            int k = kt * 64 + kk;
            int c = k / 24, rem = k - c * 24;
            float v = g_t1[(long)(b0 + r) * 1152 + c * 72 + j * 8 + rem];
            aT[kk * 130 + r] = v * bnS[c] + bnS[16 + c];
        }
        // weight tile duplicated: wD[kk][2*col]
        for (int i = t; i < 8192; i += 256) {
            int kk = i >> 7, col = i & 127;
            float v = wbase[(kt * 64 + kk) * 256 + col];
            *reinterpret_cast<float2*>(wD + kk * 258 + 2 * col) = make_float2(v, v);
        }
        __syncthreads();

        #pragma unroll 4
        for (int k = 0; k < 64; k++) {
            unsigned long long av[4];
            #pragma unroll
            for (int q = 0; q < 4; q++) av[q] = a64[k * 65 + rg + 16 * q];
            unsigned long long wv[8];
            #pragma unroll
            for (int c = 0; c < 8; c++) wv[c] = w64[k * 129 + cg * 8 + c];
            #pragma unroll
            for (int q = 0; q < 4; q++)
                #pragma unroll
                for (int c = 0; c < 8; c++) fma2(acc[q][c], av[q], wv[c]);
        }
    }
    __syncthreads();

    float* pre = sm;              // [128][129]
    #pragma unroll
    for (int q = 0; q < 4; q++)
        #pragma unroll
        for (int c = 0; c < 8; c++) {
            float2 v = *reinterpret_cast<float2*>(&acc[q][c]);
            int r0 = 2 * rg + 32 * q;
            pre[r0 * 129 + cg * 8 + c]       = v.x;
            pre[(r0 + 1) * 129 + cg * 8 + c] = v.y;
        }
    __syncthreads();

    // Pool(4,s2,p1)+relu+stats. thread = (row, half) -> 8 o2 channels
    const int row = t & 127, half = t >> 7;
    const float* pr = pre + row * 129;
    long tbase = (long)(b0 + row) * 896 + j * 4;
    #pragma unroll
    for (int ol = 0; ol < 8; ol++) {
        int lc = half * 8 + ol;             // local col group (o2 within block)
        int o2g = cb * 16 + lc;             // global o2 channel
        float s = 0.f, ss = 0.f;
        float m4[4];
        #pragma unroll
        for (int k = 0; k < 4; k++) {
            int lo = (2 * k - 1 < 0) ? 0 : 2 * k - 1;
            int hi = (2 * k + 2 > 7) ? 7 : 2 * k + 2;
            float m = pr[lc * 8 + lo];
            for (int nn = lo + 1; nn <= hi; nn++) m = fmaxf(m, pr[lc * 8 + nn]);
            m = fmaxf(m, 0.f);
            m4[k] = m;
            s += m; ss += m * m;
        }
        *reinterpret_cast<float4*>(g_t2 + tbase + o2g * 28) =
            make_float4(m4[0], m4[1], m4[2], m4[3]);
        float sA = warp_sum(s), ssA = warp_sum(ss);
        if ((t & 31) == 0) {
            atomicAdd(&g_red[32 + o2g], sA);
            atomicAdd(&g_red[64 + o2g], ssA);
        }
    }
}

// Layer3: per batch-tile of 16: full t2 slice in smem (BN2 folded on load),
// contraction over (c=32, k=3); weights transposed [k][o3] (conflict-free).
__global__ void __launch_bounds__(256) k_layer3(const float* __restrict__ w3) {
    extern __shared__ float sm[];          // acts 14336 | ws 6144
    __shared__ float st[128];
    float* acts = sm;
    float* ws = sm + 14336;                // ws[kidx][o3], kidx = c*3+r
    int t = threadIdx.x;
    int b0 = blockIdx.x * 16;
    for (int i = t; i < 14336; i += 256) {
        int k = i % 896;
        int c = k / 28;
        acts[i] = g_t2[b0 * 896 + i] * g_bn2[c] + g_bn2[32 + c];
    }
    for (int i = t; i < 6144; i += 256) {
        int kidx = i >> 6, o = i & 63;
        int c = kidx / 3, rr = kidx - c * 3;
        ws[i] = w3[(o * 32 + c) * 3 + rr];  // w3[...,0]: last dim is 1
    }
    __syncthreads();

    int o3 = t & 63, rb = t >> 6;
    const float invj[5] = {1.f, 0.5f, 0.25f, 0.125f, 0.0625f};
    float s = 0, ssq = 0;
    for (int q = 0; q < 4; q++) {
        int row = rb * 4 + q;
        const float* arow = acts + row * 896;
        float accs[15];
        #pragma unroll
        for (int i = 0; i < 15; i++) accs[i] = 0.f;
        for (int c = 0; c < 32; c++) {
            float a[28];
            const float4* a4 = reinterpret_cast<const float4*>(arow + c * 28);
            #pragma unroll
            for (int i4 = 0; i4 < 7; i4++) {
                float4 v = a4[i4];
                a[i4 * 4] = v.x; a[i4 * 4 + 1] = v.y; a[i4 * 4 + 2] = v.z; a[i4 * 4 + 3] = v.w;
            }
            float w0  = ws[(c * 3 + 0) * 64 + o3];
            float w1v = ws[(c * 3 + 1) * 64 + o3];
            float w2v = ws[(c * 3 + 2) * 64 + o3];
            #pragma unroll
            for (int jj = 0; jj < 5; jj++)
                #pragma unroll
                for (int l = 0; l < 3; l++)
                    accs[jj * 3 + l] += w0 * a[jj * 4 + l]
                                      + w1v * a[(jj + 1) * 4 + l]
                                      + w2v * a[(jj + 2) * 4 + l];
        }
        #pragma unroll
        for (int jj = 0; jj < 5; jj++) {
            float m = fmaxf(fmaxf(accs[jj * 3], accs[jj * 3 + 1]), accs[jj * 3 + 2]);
            m = fmaxf(m * invj[jj], 0.f);
            g_t3[(b0 + row) * 320 + o3 * 5 + jj] = m;
            s += m; ssq += m * m;
        }
    }
    if (t < 128) st[t] = 0.f;
    __syncthreads();
    atomicAdd(&st[o3], s);
    atomicAdd(&st[64 + o3], ssq);
    __syncthreads();
    if (t < 64) { atomicAdd(&g_red[96 + t], st[t]); atomicAdd(&g_red[160 + t], st[64 + t]); }
}

// BN3 + 3-layer MLP. One thread per sample; t3 tiles staged through smem.
__global__ void __launch_bounds__(128) k_fc(const float* __restrict__ fw1, const float* __restrict__ fb1,
                                            const float* __restrict__ fw2, const float* __restrict__ fb2,
                                            const float* __restrict__ fw3, const float* __restrict__ fb3,
                                            float* __restrict__ out) {
    __shared__ float w1s[5120];            // transposed [k][o]
    __shared__ float vt[128 * 33];
    __shared__ float w2s[256];
    __shared__ float w3s[272];
    __shared__ float b1s[16], b2s[16], b3s[17];
    int t = threadIdx.x;
    int bbase = blockIdx.x * 128;
    for (int i = t; i < 5120; i += 128) { int o = i / 320, k = i % 320; w1s[k * 16 + o] = fw1[i]; }
    for (int i = t; i < 256; i += 128) w2s[i] = fw2[i];
    for (int i = t; i < 272; i += 128) w3s[i] = fw3[i];
    if (t < 16) { b1s[t] = fb1[t]; b2s[t] = fb2[t]; }
    if (t < 17) b3s[t] = fb3[t];
    __syncthreads();

    float h1[16];
    #pragma unroll
    for (int o = 0; o < 16; o++) h1[o] = b1s[o];

    for (int i0 = 0; i0 < 320; i0 += 32) {
        __syncthreads();
        for (int idx = t; idx < 4096; idx += 128) {
            int r = idx >> 5, c2 = idx & 31;
            int i = i0 + c2, ch = i / 5;
            vt[r * 33 + c2] = g_t3[(bbase + r) * 320 + i] * g_bn3[ch] + g_bn3[64 + ch];
        }
        __syncthreads();
        #pragma unroll 4
        for (int c2 = 0; c2 < 32; c2++) {
            float v = vt[t * 33 + c2];
            const float* wr = &w1s[(i0 + c2) * 16];
            #pragma unroll
            for (int o = 0; o < 16; o++) h1[o] += v * wr[o];
        }
    }
    float h2[16];
    #pragma unroll
    for (int o = 0; o < 16; o++) {
        float a = b2s[o];
        #pragma unroll
        for (int k = 0; k < 16; k++) a += h1[k] * w2s[o * 16 + k];
        h2[o] = a;
    }
    int b = bbase + t;
    #pragma unroll
    for (int o = 0; o < 17; o++) {
        float a = b3s[o];
        #pragma unroll
        for (int k = 0; k < 16; k++) a += h2[k] * w3s[o * 16 + k];
        out[b * 17 + o] = a;
    }
}

extern "C" void kernel_launch(void* const* d_in, const int* in_sizes, int n_in,
                              void* d_out, int out_size) {
    const float* x   = (const float*)d_in[0];
    const float* w1  = (const float*)d_in[1];
    const float* w2  = (const float*)d_in[2];
    const float* w3  = (const float*)d_in[3];
    const float* g1  = (const float*)d_in[4];
    const float* b1  = (const float*)d_in[5];
    const float* g2  = (const float*)d_in[6];
    const float* b2  = (const float*)d_in[7];
    const float* g3  = (const float*)d_in[8];
    const float* b3  = (const float*)d_in[9];
    const float* fw1 = (const float*)d_in[10];
    const float* fb1 = (const float*)d_in[11];
    const float* fw2 = (const float*)d_in[12];
    const float* fb2 = (const float*)d_in[13];
    const float* fw3 = (const float*)d_in[14];
    const float* fb3 = (const float*)d_in[15];
    float* out = (float*)d_out;

    cudaFuncSetAttribute(k_layer1, cudaFuncAttributeMaxDynamicSharedMemorySize, 74496);
    cudaFuncSetAttribute(k_layer2, cudaFuncAttributeMaxDynamicSharedMemorySize, 99328);
    cudaFuncSetAttribute(k_layer3, cudaFuncAttributeMaxDynamicSharedMemorySize, 81920);

    k_zero<<<1, 256>>>();
    k_prep1<<<(221184 + 255) / 256, 256>>>(w1);
    k_prep2<<<(688128 + 255) / 256, 256>>>(w2);
    k_layer1<<<dim3(32, 18), 256, 74496>>>(x);
    k_bnparam<<<1, 64>>>(g1, b1, 1);
    k_layer2<<<dim3(32, 2, 7), 256, 99328>>>();
    k_bnparam<<<1, 64>>>(g2, b2, 2);
    k_layer3<<<256, 256, 81920>>>(w3);
    k_bnparam<<<1, 64>>>(g3, b3, 3);
    k_fc<<<32, 128>>>(fw1, fb1, fw2, fb2, fw3, fb3, out);
}

// round 7
// speedup vs baseline: 2.3379x; 1.0248x over previous
#include <cuda_runtime.h>

// ---------------- scratch (device globals; no allocation allowed) ----------------
__device__ float g_A1[221184];    // layer1 eff weights: [(o*9+j)][kk(96)][n(16)]
__device__ float g_A2[688128];    // layer2 eff weights: [j][kk(384)][col(256)] col=o*8+n
__device__ float g_t1[4718592];   // [b][c16][j9][n8]
__device__ float g_t2[3670016];   // [b][c32][j7][l4]
__device__ float g_t3[1310720];   // [b][o*5+j]
__device__ float g_red[224];      // sum1[16] ssq1[16] sum2[32] ssq2[32] sum3[64] ssq3[64]
__device__ float g_bn1[32];       // [scale16][shift16]
__device__ float g_bn2[64];       // [scale32][shift32]
__device__ float g_bn3[128];      // [scale64][shift64]

typedef unsigned long long ull;

__device__ __forceinline__ void fma2(ull& d, ull a, ull b) {
    asm("fma.rn.f32x2 %0, %1, %2, %0;" : "+l"(d) : "l"(a), "l"(b));
}
__device__ __forceinline__ ull dup2(float v) {
    ull r;
    asm("mov.b64 %0, {%1, %1};" : "=l"(r) : "f"(v));
    return r;
}
__device__ __forceinline__ float warp_sum(float v) {
    #pragma unroll
    for (int o = 16; o; o >>= 1) v += __shfl_down_sync(0xffffffffu, v, o);
    return v;
}

__global__ void k_zero() {
    if (threadIdx.x < 224) g_red[threadIdx.x] = 0.f;
}

// Build layer1 effective weights. A1[(o,j)][kk=c*16+p][n]
__global__ void k_prep1(const float* __restrict__ w1) {
    int id = blockIdx.x * blockDim.x + threadIdx.x;
    if (id >= 221184) return;
    int n  = id & 15;
    int kk = (id >> 4) % 96;
    int oj = id / 1536;
    int o = oj / 9, j = oj % 9;
    int c = kk >> 4, p = kk & 15;
    int h = 1 << j;
    int d = p - n;
    float v = 0.f;
    if (d >= -3 * h && d <= 3 * h) {
        float t = (float)d / (float)h;
        #pragma unroll
        for (int mm = 0; mm < 7; mm++) {
            float hat = 1.f - fabsf(t - (float)(mm - 3));
            if (hat > 0.f) v += w1[(o * 6 + c) * 7 + mm] * hat;
        }
        v /= (float)h;
    }
    g_A1[id] = v;
}

// Build layer2 effective weights. A2[j][kk=(c*3+r)*8+p][col=o*8+n]
__global__ void k_prep2(const float* __restrict__ w2) {
    int id = blockIdx.x * blockDim.x + threadIdx.x;
    if (id >= 688128) return;
    int col = id & 255;
    int kk  = (id >> 8) % 384;
    int j   = id / 98304;
    int o = col >> 3, n = col & 7;
    int p = kk & 7;
    int cr = kk >> 3;               // c*3+r
    int h = 1 << j;
    int d = p - n;
    float v = 0.f;
    if (d >= -h && d <= h) {
        float t = (float)d / (float)h;
        #pragma unroll
        for (int mm = 0; mm < 3; mm++) {
            float hat = 1.f - fabsf(t - (float)(mm - 1));
            if (hat > 0.f) v += w2[(o * 48 + cr) * 3 + mm] * hat;
        }
        v /= (float)h;
    }
    g_A2[id] = v;
}

// ---------------------------------------------------------------------------
// Layer1: C[4096 x 2304] = X[4096 x 96] * A1[96 x 2304], fused pool+relu+stats.
// Block 128 rows x 64 cols, 256 threads, per-thread 4 row-pairs x 4 cols (f32x2).
// aT[k][row] transposed; wD[k][2*col] duplicated. 4 blocks/SM target.
// smem floats: aT 48*130=6240 | wD 48*130=6240 => 49920 B. K in 2 tiles of 48.
// ---------------------------------------------------------------------------
__global__ void __launch_bounds__(256, 4) k_layer1(const float* __restrict__ x) {
    extern __shared__ float sm[];
    float* aT = sm;               // [48][130]
    float* wD = sm + 6240;        // [48][130] dup cols (64 col-pairs + pad)
    const int t = threadIdx.x;
    const int b0  = blockIdx.x * 128;
    const int oj0 = blockIdx.y * 4;

    const int rg = t & 15, cg = t >> 4;   // row-pairs 2rg+32q, cols cg*4..+3
    ull acc[4][4];
    #pragma unroll
    for (int q = 0; q < 4; q++)
        #pragma unroll
        for (int c = 0; c < 4; c++) acc[q][c] = 0ull;

    const ull* a64 = reinterpret_cast<const ull*>(aT);
    const ull* w64 = reinterpret_cast<const ull*>(wD);

    for (int kt = 0; kt < 2; kt++) {
        __syncthreads();
        // acts transposed: aT[kk][r]
        for (int i = t; i < 6144; i += 256) {
            int r = i / 48, kk = i - r * 48;
            aT[kk * 130 + r] = x[(b0 + r) * 96 + kt * 48 + kk];
        }
        // weights duplicated: wD[kk][2*col] = {w,w}, col < 64
        for (int i = t; i < 3072; i += 256) {
            int kk = i >> 6, col = i & 63;
            int g = col >> 4, n = col & 15;
            float v = g_A1[(oj0 + g) * 1536 + (kt * 48 + kk) * 16 + n];
            *reinterpret_cast<float2*>(wD + kk * 130 + 2 * col) = make_float2(v, v);
        }
        __syncthreads();

        #pragma unroll 4
        for (int k = 0; k < 48; k++) {
            ull av[4];
            #pragma unroll
            for (int q = 0; q < 4; q++) av[q] = a64[k * 65 + rg + 16 * q];
            ull wv[4];
            #pragma unroll
            for (int c = 0; c < 4; c++) wv[c] = w64[k * 65 + cg * 4 + c];
            #pragma unroll
            for (int q = 0; q < 4; q++)
                #pragma unroll
                for (int c = 0; c < 4; c++) fma2(acc[q][c], av[q], wv[c]);
        }
    }
    __syncthreads();

    // pre[128][65] reuses smem
    float* pre = sm;
    #pragma unroll
    for (int q = 0; q < 4; q++)
        #pragma unroll
        for (int c = 0; c < 4; c++) {
            float2 v = *reinterpret_cast<float2*>(&acc[q][c]);
            int r0 = 2 * rg + 32 * q;
            pre[r0 * 65 + cg * 4 + c]       = v.x;
            pre[(r0 + 1) * 65 + cg * 4 + c] = v.y;
        }
    __syncthreads();

    // Pool(4,s2,p1)+relu+stats. thread = (row = t&127, half = t>>7) -> 2 oj groups
    const int row = t & 127, half = t >> 7;
    const float* pr = pre + row * 65;
    long base = (long)(b0 + row) * 1152;
    #pragma unroll
    for (int gg = 0; gg < 2; gg++) {
        int g = half * 2 + gg;
        int oj = oj0 + g;
        int o = oj / 9, jj = oj - o * 9;
        float* dst = g_t1 + base + o * 72 + jj * 8;
        float s = 0.f, ss = 0.f;
        float m8[8];
        #pragma unroll
        for (int k = 0; k < 8; k++) {
            int lo = (2 * k - 1 < 0) ? 0 : 2 * k - 1;
            int hi = (2 * k + 2 > 15) ? 15 : 2 * k + 2;
            float m = pr[g * 16 + lo];
            for (int nn = lo + 1; nn <= hi; nn++) m = fmaxf(m, pr[g * 16 + nn]);
            m = fmaxf(m, 0.f);
            m8[k] = m;
            s += m; ss += m * m;
        }
        *reinterpret_cast<float4*>(dst)     = make_float4(m8[0], m8[1], m8[2], m8[3]);
        *reinterpret_cast<float4*>(dst + 4) = make_float4(m8[4], m8[5], m8[6], m8[7]);
        float sA = warp_sum(s), ssA = warp_sum(ss);
        if ((t & 31) == 0) {
            atomicAdd(&g_red[o], sA);
            atomicAdd(&g_red[16 + o], ssA);
        }
    }
}

__global__ void k_bnparam(const float* __restrict__ g, const float* __restrict__ b, int layer) {
    int c = threadIdx.x;
    int nch, off; float count; float* bn;
    if (layer == 1)      { nch = 16; off = 0;  count = 294912.f; bn = g_bn1; }
    else if (layer == 2) { nch = 32; off = 32; count = 114688.f; bn = g_bn2; }
    else                 { nch = 64; off = 96; count = 20480.f;  bn = g_bn3; }
    if (c >= nch) return;
    float sum = g_red[off + c], ssq = g_red[off + nch + c];
    float mean = sum / count;
    float var = ssq / count - mean * mean;
    float sc = g[c] * rsqrtf(var + 2e-5f);
    bn[c] = sc;
    bn[nch + c] = b[c] - mean * sc;
}

// ---------------------------------------------------------------------------
// Layer2: per j: C[4096 x 256] = acts[4096 x 384] * A2[j], BN1 folded,
// fused pool+relu+stats. Block 128 rows x 64 cols (8 o2), 256 threads,
// 4x4 row-pair f32x2. K in 6 tiles of 64. 3 blocks/SM target.
// smem floats: aT 64*130=8320 | wD 64*130=8320 => 66560 B
// ---------------------------------------------------------------------------
__global__ void __launch_bounds__(256, 3) k_layer2() {
    extern __shared__ float sm[];
    __shared__ float bnS[32];
    float* aT = sm;               // [64][130]
    float* wD = sm + 8320;        // [64][130]
    const int t = threadIdx.x;
    const int b0 = blockIdx.x * 128;
    const int cb = blockIdx.y;    // col block: o2 channels cb*8..+7
    const int j  = blockIdx.z;

    if (t < 32) bnS[t] = g_bn1[t];

    const int rg = t & 15, cg = t >> 4;
    ull acc[4][4];
    #pragma unroll
    for (int q = 0; q < 4; q++)
        #pragma unroll
        for (int c = 0; c < 4; c++) acc[q][c] = 0ull;

    const ull* a64 = reinterpret_cast<const ull*>(aT);
    const ull* w64 = reinterpret_cast<const ull*>(wD);
    const float* wbase = g_A2 + j * 98304 + cb * 64;

    for (int kt = 0; kt < 6; kt++) {
        __syncthreads();
        // acts tile transposed (BN1 folded): aT[kk][r]
        for (int i = t; i < 8192; i += 256) {
            int r = i >> 6, kk = i & 63;
            int k = kt * 64 + kk;
            int c = k / 24, rem = k - c * 24;
            float v = g_t1[(long)(b0 + r) * 1152 + c * 72 + j * 8 + rem];
            aT[kk * 130 + r] = v * bnS[c] + bnS[16 + c];
        }
        // weight tile duplicated: wD[kk][2*col], col < 64
        for (int i = t; i < 4096; i += 256) {
            int kk = i >> 6, col = i & 63;
            float v = wbase[(kt * 64 + kk) * 256 + col];
            *reinterpret_cast<float2*>(wD + kk * 130 + 2 * col) = make_float2(v, v);
        }
        __syncthreads();

        #pragma unroll 4
        for (int k = 0; k < 64; k++) {
            ull av[4];
            #pragma unroll
            for (int q = 0; q < 4; q++) av[q] = a64[k * 65 + rg + 16 * q];
            ull wv[4];
            #pragma unroll
            for (int c = 0; c < 4; c++) wv[c] = w64[k * 65 + cg * 4 + c];
            #pragma unroll
            for (int q = 0; q < 4; q++)
                #pragma unroll
                for (int c = 0; c < 4; c++) fma2(acc[q][c], av[q], wv[c]);
        }
    }
    __syncthreads();

    float* pre = sm;              // [128][65]
    #pragma unroll
    for (int q = 0; q < 4; q++)
        #pragma unroll
        for (int c = 0; c < 4; c++) {
            float2 v = *reinterpret_cast<float2*>(&acc[q][c]);
            int r0 = 2 * rg + 32 * q;
            pre[r0 * 65 + cg * 4 + c]       = v.x;
            pre[(r0 + 1) * 65 + cg * 4 + c] = v.y;
        }
    __syncthreads();

    // Pool(4,s2,p1)+relu+stats. thread = (row, half) -> 4 o2 channels
    const int row = t & 127, half = t >> 7;
    const float* pr = pre + row * 65;
    long tbase = (long)(b0 + row) * 896 + j * 4;
    #pragma unroll
    for (int ol = 0; ol < 4; ol++) {
        int lc = half * 4 + ol;             // local col group within block (0..7)
        int o2g = cb * 8 + lc;              // global o2 channel
        float s = 0.f, ss = 0.f;
        float m4[4];
        #pragma unroll
        for (int k = 0; k < 4; k++) {
            int lo = (2 * k - 1 < 0) ? 0 : 2 * k - 1;
            int hi = (2 * k + 2 > 7) ? 7 : 2 * k + 2;
            float m = pr[lc * 8 + lo];
            for (int nn = lo + 1; nn <= hi; nn++) m = fmaxf(m, pr[lc * 8 + nn]);
            m = fmaxf(m, 0.f);
            m4[k] = m;
            s += m; ss += m * m;
        }
        *reinterpret_cast<float4*>(g_t2 + tbase + o2g * 28) =
            make_float4(m4[0], m4[1], m4[2], m4[3]);
        float sA = warp_sum(s), ssA = warp_sum(ss);
        if ((t & 31) == 0) {
            atomicAdd(&g_red[32 + o2g], sA);
            atomicAdd(&g_red[64 + o2g], ssA);
        }
    }
}

// ---------------------------------------------------------------------------
// Layer3: per batch-tile of 16 rows. acts transposed [idx 896][18] (BN2 folded)
// so row-pairs are natural LDS.64 (warp-uniform broadcast). Weights [kidx][o3].
// Row-pair f32x2 accumulation halves fma-pipe time vs scalar.
// smem floats: actsT 896*18=16128 | ws 96*64=6144 => 89088 B. 2 blocks/SM.
// ---------------------------------------------------------------------------
__global__ void __launch_bounds__(256, 2) k_layer3(const float* __restrict__ w3) {
    extern __shared__ float sm[];
    float* actsT = sm;             // [896][18]
    float* ws    = sm + 16128;     // [96][64]
    __shared__ float st[128];
    const int t = threadIdx.x;
    const int b0 = blockIdx.x * 16;

    for (int i = t; i < 14336; i += 256) {
        int r = i / 896, idx = i - r * 896;
        int c = idx / 28;
        actsT[idx * 18 + r] = g_t2[(long)b0 * 896 + i] * g_bn2[c] + g_bn2[32 + c];
    }
    for (int i = t; i < 6144; i += 256) {
        int kidx = i >> 6, o = i & 63;
        int c = kidx / 3, rr = kidx - c * 3;
        ws[i] = w3[(o * 32 + c) * 3 + rr];  // w3[...,0]: last dim is 1
    }
    if (t < 128) st[t] = 0.f;
    __syncthreads();

    const int o3 = t & 63, rpg = t >> 6;   // rpg warp-uniform
    const ull* a64 = reinterpret_cast<const ull*>(actsT);  // stride 9 per idx
    const float invj[5] = {1.f, 0.5f, 0.25f, 0.125f, 0.0625f};
    float s = 0.f, ssq = 0.f;

    #pragma unroll
    for (int hf = 0; hf < 2; hf++) {
        const int rp = rpg + 4 * hf;       // row-pair: rows 2rp, 2rp+1
        ull accp[15];
        #pragma unroll
        for (int i = 0; i < 15; i++) accp[i] = 0ull;

        for (int c = 0; c < 32; c++) {
            ull av[21];                    // [m 0..6][l 0..2] row-pairs (broadcast)
            #pragma unroll
            for (int m = 0; m < 7; m++)
                #pragma unroll
                for (int l = 0; l < 3; l++)
                    av[m * 3 + l] = a64[(c * 28 + m * 4 + l) * 9 + rp];
            ull w0 = dup2(ws[(c * 3 + 0) * 64 + o3]);
            ull w1 = dup2(ws[(c * 3 + 1) * 64 + o3]);
            ull w2 = dup2(ws[(c * 3 + 2) * 64 + o3]);
            #pragma unroll
            for (int jj = 0; jj < 5; jj++)
                #pragma unroll
                for (int l = 0; l < 3; l++) {
                    fma2(accp[jj * 3 + l], w0, av[(jj + 0) * 3 + l]);
                    fma2(accp[jj * 3 + l], w1, av[(jj + 1) * 3 + l]);
                    fma2(accp[jj * 3 + l], w2, av[(jj + 2) * 3 + l]);
                }
        }
        // pool over l + relu + scale, both rows of the pair
        #pragma unroll
        for (int jj = 0; jj < 5; jj++) {
            float2 v0 = *reinterpret_cast<float2*>(&accp[jj * 3 + 0]);
            float2 v1 = *reinterpret_cast<float2*>(&accp[jj * 3 + 1]);
            float2 v2 = *reinterpret_cast<float2*>(&accp[jj * 3 + 2]);
            float mx = fmaxf(fmaxf(v0.x, v1.x), v2.x) * invj[jj];
            float my = fmaxf(fmaxf(v0.y, v1.y), v2.y) * invj[jj];
            mx = fmaxf(mx, 0.f); my = fmaxf(my, 0.f);
            g_t3[(b0 + 2 * rp) * 320 + o3 * 5 + jj]     = mx;
            g_t3[(b0 + 2 * rp + 1) * 320 + o3 * 5 + jj] = my;
            s += mx + my; ssq += mx * mx + my * my;
        }
    }
    atomicAdd(&st[o3], s);
    atomicAdd(&st[64 + o3], ssq);
    __syncthreads();
    if (t < 64) { atomicAdd(&g_red[96 + t], st[t]); atomicAdd(&g_red[160 + t], st[64 + t]); }
}

// BN3 + 3-layer MLP. One thread per sample; t3 tiles staged through smem.
__global__ void __launch_bounds__(128) k_fc(const float* __restrict__ fw1, const float* __restrict__ fb1,
                                            const float* __restrict__ fw2, const float* __restrict__ fb2,
                                            const float* __restrict__ fw3, const float* __restrict__ fb3,
                                            float* __restrict__ out) {
    __shared__ float w1s[5120];            // transposed [k][o]
    __shared__ float vt[128 * 33];
    __shared__ float w2s[256];
    __shared__ float w3s[272];
    __shared__ float b1s[16], b2s[16], b3s[17];
    int t = threadIdx.x;
    int bbase = blockIdx.x * 128;
    for (int i = t; i < 5120; i += 128) { int o = i / 320, k = i % 320; w1s[k * 16 + o] = fw1[i]; }
    for (int i = t; i < 256; i += 128) w2s[i] = fw2[i];
    for (int i = t; i < 272; i += 128) w3s[i] = fw3[i];
    if (t < 16) { b1s[t] = fb1[t]; b2s[t] = fb2[t]; }
    if (t < 17) b3s[t] = fb3[t];
    __syncthreads();

    float h1[16];
    #pragma unroll
    for (int o = 0; o < 16; o++) h1[o] = b1s[o];

    for (int i0 = 0; i0 < 320; i0 += 32) {
        __syncthreads();
        for (int idx = t; idx < 4096; idx += 128) {
            int r = idx >> 5, c2 = idx & 31;
            int i = i0 + c2, ch = i / 5;
            vt[r * 33 + c2] = g_t3[(bbase + r) * 320 + i] * g_bn3[ch] + g_bn3[64 + ch];
        }
        __syncthreads();
        #pragma unroll 4
        for (int c2 = 0; c2 < 32; c2++) {
            float v = vt[t * 33 + c2];
            const float* wr = &w1s[(i0 + c2) * 16];
            #pragma unroll
            for (int o = 0; o < 16; o++) h1[o] += v * wr[o];
        }
    }
    float h2[16];
    #pragma unroll
    for (int o = 0; o < 16; o++) {
        float a = b2s[o];
        #pragma unroll
        for (int k = 0; k < 16; k++) a += h1[k] * w2s[o * 16 + k];
        h2[o] = a;
    }
    int b = bbase + t;
    #pragma unroll
    for (int o = 0; o < 17; o++) {
        float a = b3s[o];
        #pragma unroll
        for (int k = 0; k < 16; k++) a += h2[k] * w3s[o * 16 + k];
        out[b * 17 + o] = a;
    }
}

extern "C" void kernel_launch(void* const* d_in, const int* in_sizes, int n_in,
                              void* d_out, int out_size) {
    const float* x   = (const float*)d_in[0];
    const float* w1  = (const float*)d_in[1];
    const float* w2  = (const float*)d_in[2];
    const float* w3  = (const float*)d_in[3];
    const float* g1  = (const float*)d_in[4];
    const float* b1  = (const float*)d_in[5];
    const float* g2  = (const float*)d_in[6];
    const float* b2  = (const float*)d_in[7];
    const float* g3  = (const float*)d_in[8];
    const float* b3  = (const float*)d_in[9];
    const float* fw1 = (const float*)d_in[10];
    const float* fb1 = (const float*)d_in[11];
    const float* fw2 = (const float*)d_in[12];
    const float* fb2 = (const float*)d_in[13];
    const float* fw3 = (const float*)d_in[14];
    const float* fb3 = (const float*)d_in[15];
    float* out = (float*)d_out;

    cudaFuncSetAttribute(k_layer1, cudaFuncAttributeMaxDynamicSharedMemorySize, 49920);
    cudaFuncSetAttribute(k_layer2, cudaFuncAttributeMaxDynamicSharedMemorySize, 66560);
    cudaFuncSetAttribute(k_layer3, cudaFuncAttributeMaxDynamicSharedMemorySize, 89088);

    k_zero<<<1, 256>>>();
    k_prep1<<<(221184 + 255) / 256, 256>>>(w1);
    k_prep2<<<(688128 + 255) / 256, 256>>>(w2);
    k_layer1<<<dim3(32, 36), 256, 49920>>>(x);
    k_bnparam<<<1, 64>>>(g1, b1, 1);
    k_layer2<<<dim3(32, 4, 7), 256, 66560>>>();
    k_bnparam<<<1, 64>>>(g2, b2, 2);
    k_layer3<<<256, 256, 89088>>>(w3);
    k_bnparam<<<1, 64>>>(g3, b3, 3);
    k_fc<<<32, 128>>>(fw1, fb1, fw2, fb2, fw3, fb3, out);
}